// round 14
// baseline (speedup 1.0000x reference)
#include <cuda_runtime.h>
#include <cuda_bf16.h>
#include <cstdint>

// ============================================================================
// CustomConvLayer: 9 bilinear taps @ integer+0.4 == exact 4x4 conv (folded).
// HMMA (mma.sync m16n8k16 bf16) implicit GEMM, bf16x3 split for fp32 accuracy.
// R14: wide tile TX=32 (8x32 px/CTA, 512 CTAs). Per tap per warp: 48 MMAs vs
//      unchanged 4 B-LDG.128 + loop overhead -> overhead per MMA halved.
//      Otherwise exactly the proven R8 config: 2 CTAs/SM, double-buffered B,
//      simple LDG->cvt->STS staging.
//   x: [8,64,128,128] f32   w: [64,64,9] f32   taps: [9,2] f32
//   out: [8,64,128,128] f32
// ============================================================================

#define B_    8
#define CIN   64
#define COUT  64
#define HW    128
#define NTAP  9

// pixel tile per CTA: 8 (y) x 32 (x); patch 11 x 35 pixels
#define TY 8
#define TX 32
#define IY 11
#define IX 35
#define NPX (IY * IX)            // 385
#define PITCH 48                 // bytes per pixel row (16 bf16 = 32B, padded)
#define PHALF (NPX * PITCH)      // 18480 B per half (hi / lo)
#define STAGE_N (16 * NPX)       // 6160 elements per chunk

// permuted per-lane fragments: [tap][chunk][nh][part(4)][lane(32)] of uint4
//  part0/1 = hi (nb 0,1 / nb 2,3), part2/3 = lo
__device__ uint4 g_wperm[16 * 4 * 2 * 4 * 32];   // 256 KB

// ---------------------------------------------------------------------------
// Merged prep: fold 9 taps -> 4x4, bf16 hi/lo split, scatter directly into
// the per-lane fragment layout consumed by load_b (validated in R8/R12).
// ---------------------------------------------------------------------------
__global__ void prep_kernel(const float* __restrict__ w,
                            const float* __restrict__ off) {
    int idx = blockIdx.x * blockDim.x + threadIdx.x;
    if (idx >= COUT * CIN) return;
    int o = idx >> 6, i = idx & 63;
    float acc[16];
#pragma unroll
    for (int t = 0; t < 16; t++) acc[t] = 0.f;
#pragma unroll
    for (int k = 0; k < NTAP; k++) {
        float dy = off[2 * k + 0];
        float dx = off[2 * k + 1];
        float fyf = floorf(dy), fxf = floorf(dx);
        int iy = (int)fyf, ix = (int)fxf;
        float fy = dy - fyf, fx = dx - fxf;
        float wk = w[(o * CIN + i) * NTAP + k];
        acc[iy * 4 + ix]           += wk * (1.f - fy) * (1.f - fx);
        acc[iy * 4 + ix + 1]       += wk * (1.f - fy) * fx;
        acc[(iy + 1) * 4 + ix]     += wk * fy * (1.f - fx);
        acc[(iy + 1) * 4 + ix + 1] += wk * fy * fx;
    }
    const int nh = o >> 5, nb = (o >> 3) & 3, g = o & 7;
    const int chunk = i >> 4, r = i & 15;
    const int reg = (r >> 3) & 1, tig = (r & 7) >> 1, byt = r & 1;
    const int lane = g * 4 + tig;
    const int comp = (nb & 1) * 2 + reg;
    __nv_bfloat16* wp = (__nv_bfloat16*)g_wperm;
#pragma unroll
    for (int t = 0; t < 16; t++) {
        float v = acc[t];
        __nv_bfloat16 h = __float2bfloat16(v);
        __nv_bfloat16 l = __float2bfloat16(v - __bfloat162float(h));
        size_t slab = (size_t)((t * 4 + chunk) * 2 + nh) * 4;
        wp[((slab + (nb >> 1)) * 32 + lane) * 8 + comp * 2 + byt]     = h;
        wp[((slab + 2 + (nb >> 1)) * 32 + lane) * 8 + comp * 2 + byt] = l;
    }
}

// ---------------------------------------------------------------------------
__device__ __forceinline__ uint32_t smem_to_u32(const void* p) {
    uint32_t a;
    asm("{ .reg .u64 t; cvta.to.shared.u64 t, %1; cvt.u32.u64 %0, t; }"
        : "=r"(a) : "l"(p));
    return a;
}

#define LDSM4(r, addr) \
    asm volatile("ldmatrix.sync.aligned.m8n8.x4.shared.b16 {%0,%1,%2,%3}, [%4];" \
                 : "=r"((r)[0]), "=r"((r)[1]), "=r"((r)[2]), "=r"((r)[3]) \
                 : "r"(addr))

#define MMA16816(c, a, bb) \
    asm("mma.sync.aligned.m16n8k16.row.col.f32.bf16.bf16.f32 " \
        "{%0,%1,%2,%3}, {%4,%5,%6,%7}, {%8,%9}, {%0,%1,%2,%3};" \
        : "+f"((c)[0]), "+f"((c)[1]), "+f"((c)[2]), "+f"((c)[3]) \
        : "r"((a)[0]), "r"((a)[1]), "r"((a)[2]), "r"((a)[3]), \
          "r"((bb)[0]), "r"((bb)[1]))

// coalesced B load: 4 x LDG.128 per (tap, chunk)
__device__ __forceinline__ void load_b(const uint4* wp,
                                       uint32_t bh[4][2], uint32_t bl[4][2]) {
    uint4 h0 = wp[0], h1 = wp[32], l0 = wp[64], l1 = wp[96];
    bh[0][0] = h0.x; bh[0][1] = h0.y; bh[1][0] = h0.z; bh[1][1] = h0.w;
    bh[2][0] = h1.x; bh[2][1] = h1.y; bh[3][0] = h1.z; bh[3][1] = h1.w;
    bl[0][0] = l0.x; bl[0][1] = l0.y; bl[1][0] = l0.z; bl[1][1] = l0.w;
    bl[2][0] = l1.x; bl[2][1] = l1.y; bl[3][0] = l1.z; bl[3][1] = l1.w;
}

// ---------------------------------------------------------------------------
// 256 threads, 8 warps. Warp w: y rows {2*(w%4), 2*(w%4)+1} x 32 cols
// (4 m16 tiles), couts (w/4)*32..+31.
// ---------------------------------------------------------------------------
__global__ __launch_bounds__(256, 2)
void conv_hmma_kernel(const float* __restrict__ x, float* __restrict__ out) {
    __shared__ __align__(16) char patch[2 * PHALF];   // hi then lo, 36960 B

    const int tid  = threadIdx.x;
    const int lane = tid & 31;
    const int w    = tid >> 5;
    const int wy   = w & 3;                 // y-pair index
    const int nh   = w >> 2;                // cout half
    const int nbase = nh * 32;
    const int g   = lane >> 2;
    const int tig = lane & 3;

    const int b  = blockIdx.z;
    const int y0 = blockIdx.y * TY;
    const int x0 = blockIdx.x * TX;

    const uint32_t sbase = smem_to_u32(patch);
    const uint32_t laneoff =
        (uint32_t)(((lane & 7) + ((lane >> 3) & 1) * 8) * PITCH + (lane >> 4) * 16);

    // acc[m][nb][q], m = yr*2 + xh (yr: y-row 0/1, xh: x-half 0/1)
    float acc[4][4][4];
#pragma unroll
    for (int m = 0; m < 4; m++)
#pragma unroll
        for (int nb = 0; nb < 4; nb++)
#pragma unroll
            for (int q = 0; q < 4; q++) acc[m][nb][q] = 0.f;

    const float* xb = x + (size_t)b * CIN * HW * HW;

    for (int chunk = 0; chunk < 4; chunk++) {
        __syncthreads();   // protect previous chunk's reads
        // ---- stage patch: 16 cin x 385 px, fp32 -> bf16 hi/lo ----
        for (int idx = tid; idx < STAGE_N; idx += 256) {
            int cl = idx / NPX;
            int px = idx - cl * NPX;
            int py = px / IX, pxx = px - py * IX;
            int gy = y0 + py - 1, gx = x0 + pxx - 1;
            float v = 0.f;
            if ((unsigned)gy < (unsigned)HW && (unsigned)gx < (unsigned)HW)
                v = xb[((size_t)(chunk * 16 + cl) * HW + gy) * HW + gx];
            __nv_bfloat16 h = __float2bfloat16(v);
            __nv_bfloat16 l = __float2bfloat16(v - __bfloat162float(h));
            *(__nv_bfloat16*)(patch + px * PITCH + cl * 2) = h;
            *(__nv_bfloat16*)(patch + PHALF + px * PITCH + cl * 2) = l;
        }
        __syncthreads();

        // per-warp base into permuted weights for this chunk
        const uint4* wp0 = g_wperm + (((0 * 4 + chunk) * 2 + nh) * 4) * 32 + lane;
        #define TAPSTRIDE 1024   // uint4 stride between taps

        // ---- tap loop, B double-buffered in registers ----
        uint32_t bh[2][4][2], bl[2][4][2];
        load_b(wp0, bh[0], bl[0]);

#pragma unroll
        for (int tap = 0; tap < 16; tap++) {
            const int cur = tap & 1;
            if (tap < 15)
                load_b(wp0 + (tap + 1) * TAPSTRIDE, bh[cur ^ 1], bl[cur ^ 1]);

            const int dy = tap >> 2, dx = tap & 3;
#pragma unroll
            for (int m = 0; m < 4; m++) {
                const int yr = m >> 1, xh = m & 1;
                const int sy = wy * 2 + yr + dy;
                const uint32_t abase =
                    sbase + (uint32_t)((sy * IX + dx + xh * 16) * PITCH) + laneoff;
                uint32_t ah[4], al[4];
                LDSM4(ah, abase);
                LDSM4(al, abase + PHALF);
#pragma unroll
                for (int nb = 0; nb < 4; nb++) {
                    MMA16816(acc[m][nb], ah, bh[cur][nb]);
                    MMA16816(acc[m][nb], ah, bl[cur][nb]);
                    MMA16816(acc[m][nb], al, bh[cur][nb]);
                }
            }
        }
    }

    // ---- epilogue ----
    // c-frag: c0 = (x=g,   cout=tig*2), c1 = (x=g,   cout=tig*2+1)
    //         c2 = (x=g+8, cout=tig*2), c3 = (x=g+8, cout=tig*2+1)
#pragma unroll
    for (int m = 0; m < 4; m++) {
        const int yr = m >> 1, xh = m & 1;
        const int gy = y0 + wy * 2 + yr;
        const int gx = x0 + xh * 16;
#pragma unroll
        for (int nb = 0; nb < 4; nb++) {
            const int n = nbase + nb * 8 + tig * 2;
            float* o0 = out + ((size_t)b * COUT + n) * (HW * HW) + (size_t)gy * HW;
            float* o1 = o0 + (size_t)(HW * HW);
            o0[gx + g]     = acc[m][nb][0];
            o1[gx + g]     = acc[m][nb][1];
            o0[gx + g + 8] = acc[m][nb][2];
            o1[gx + g + 8] = acc[m][nb][3];
        }
    }
}

extern "C" void kernel_launch(void* const* d_in, const int* in_sizes, int n_in,
                              void* d_out, int out_size) {
    const float* x   = (const float*)d_in[0];
    const float* w   = (const float*)d_in[1];
    const float* off = (const float*)d_in[2];
    float* out = (float*)d_out;

    prep_kernel<<<(COUT * CIN + 255) / 256, 256>>>(w, off);

    dim3 grid(HW / TX, HW / TY, B_);   // (4, 16, 8) = 512 CTAs
    conv_hmma_kernel<<<grid, 256>>>(x, out);
}

// round 15
// speedup vs baseline: 1.3780x; 1.3780x over previous
#include <cuda_runtime.h>
#include <cuda_bf16.h>
#include <cstdint>

// ============================================================================
// CustomConvLayer: 9 bilinear taps @ integer+0.4 == exact 4x4 conv (folded).
// HMMA (mma.sync m16n8k16 bf16) implicit GEMM, bf16x3 split for fp32 accuracy.
// R15: warp = 1 m-tile x 8 n-tiles (LDSM halved, 8 indep acc chains,
//      prod-outer MMA order), B staged per-chunk into SMEM via cp.async
//      (no B reg double-buffer, no per-tap global latency coupling).
//      Same acc budget as proven R8 -> spill-free at 128-reg cap.
//   x: [8,64,128,128] f32   w: [64,64,9] f32   taps: [9,2] f32
//   out: [8,64,128,128] f32
// ============================================================================

#define B_    8
#define CIN   64
#define COUT  64
#define HW    128
#define NTAP  9

// pixel tile per CTA: 8 (y) x 16 (x); patch 11 x 19 pixels
#define TY 8
#define TX 16
#define IY 11
#define IX 19
#define NPX (IY * IX)            // 209
#define PITCH 48                 // bytes per pixel row (16 bf16 = 32B, padded)
#define PHALF (NPX * PITCH)      // 10032 B per half (hi / lo)
#define STAGE_N (16 * NPX)       // 3344 elements per chunk

// dynamic SMEM map: B stage [0, 65536), patch hi/lo [65536, 65536+2*PHALF)
#define SM_B     0
#define SM_PATCH 65536
#define SMEM_TOTAL (65536 + 2 * PHALF)   // 85600 B

// permuted per-lane fragments: [tap][chunk][nh][part(4)][lane(32)] of uint4
//  part0/1 = hi (nb 0,1 / nb 2,3), part2/3 = lo
__device__ uint4 g_wperm[16 * 4 * 2 * 4 * 32];   // 256 KB

// ---------------------------------------------------------------------------
// Merged prep: fold 9 taps -> 4x4, bf16 hi/lo split, scatter directly into
// the per-lane fragment layout (validated R8/R12).
// ---------------------------------------------------------------------------
__global__ void prep_kernel(const float* __restrict__ w,
                            const float* __restrict__ off) {
    int idx = blockIdx.x * blockDim.x + threadIdx.x;
    if (idx >= COUT * CIN) return;
    int o = idx >> 6, i = idx & 63;
    float acc[16];
#pragma unroll
    for (int t = 0; t < 16; t++) acc[t] = 0.f;
#pragma unroll
    for (int k = 0; k < NTAP; k++) {
        float dy = off[2 * k + 0];
        float dx = off[2 * k + 1];
        float fyf = floorf(dy), fxf = floorf(dx);
        int iy = (int)fyf, ix = (int)fxf;
        float fy = dy - fyf, fx = dx - fxf;
        float wk = w[(o * CIN + i) * NTAP + k];
        acc[iy * 4 + ix]           += wk * (1.f - fy) * (1.f - fx);
        acc[iy * 4 + ix + 1]       += wk * (1.f - fy) * fx;
        acc[(iy + 1) * 4 + ix]     += wk * fy * (1.f - fx);
        acc[(iy + 1) * 4 + ix + 1] += wk * fy * fx;
    }
    const int nh = o >> 5, nb = (o >> 3) & 3, g = o & 7;
    const int chunk = i >> 4, r = i & 15;
    const int reg = (r >> 3) & 1, tig = (r & 7) >> 1, byt = r & 1;
    const int lane = g * 4 + tig;
    const int comp = (nb & 1) * 2 + reg;
    __nv_bfloat16* wp = (__nv_bfloat16*)g_wperm;
#pragma unroll
    for (int t = 0; t < 16; t++) {
        float v = acc[t];
        __nv_bfloat16 h = __float2bfloat16(v);
        __nv_bfloat16 l = __float2bfloat16(v - __bfloat162float(h));
        size_t slab = (size_t)((t * 4 + chunk) * 2 + nh) * 4;
        wp[((slab + (nb >> 1)) * 32 + lane) * 8 + comp * 2 + byt]     = h;
        wp[((slab + 2 + (nb >> 1)) * 32 + lane) * 8 + comp * 2 + byt] = l;
    }
}

// ---------------------------------------------------------------------------
__device__ __forceinline__ uint32_t smem_to_u32(const void* p) {
    uint32_t a;
    asm("{ .reg .u64 t; cvta.to.shared.u64 t, %1; cvt.u32.u64 %0, t; }"
        : "=r"(a) : "l"(p));
    return a;
}

__device__ __forceinline__ void cp_async16(uint32_t saddr, const void* gptr) {
    asm volatile("cp.async.cg.shared.global [%0], [%1], 16;"
                 :: "r"(saddr), "l"(gptr));
}
#define CP_COMMIT() asm volatile("cp.async.commit_group;" ::: "memory")
#define CP_WAIT0()  asm volatile("cp.async.wait_group 0;" ::: "memory")

#define LDSM4(r, addr) \
    asm volatile("ldmatrix.sync.aligned.m8n8.x4.shared.b16 {%0,%1,%2,%3}, [%4];" \
                 : "=r"((r)[0]), "=r"((r)[1]), "=r"((r)[2]), "=r"((r)[3]) \
                 : "r"(addr))

#define LDS128(r0, r1, r2, r3, addr) \
    asm volatile("ld.shared.v4.u32 {%0, %1, %2, %3}, [%4];" \
                 : "=r"(r0), "=r"(r1), "=r"(r2), "=r"(r3) : "r"(addr))

#define MMA16816(c, a, bb) \
    asm("mma.sync.aligned.m16n8k16.row.col.f32.bf16.bf16.f32 " \
        "{%0,%1,%2,%3}, {%4,%5,%6,%7}, {%8,%9}, {%0,%1,%2,%3};" \
        : "+f"((c)[0]), "+f"((c)[1]), "+f"((c)[2]), "+f"((c)[3]) \
        : "r"((a)[0]), "r"((a)[1]), "r"((a)[2]), "r"((a)[3]), \
          "r"((bb)[0]), "r"((bb)[1]))

// ---------------------------------------------------------------------------
// 256 threads, 8 warps. Warp w: m-tile = y-row w (16 x-pixels),
// all 8 n8-tiles (64 couts).
// ---------------------------------------------------------------------------
__global__ __launch_bounds__(256, 2)
void conv_hmma_kernel(const float* __restrict__ x, float* __restrict__ out) {
    extern __shared__ __align__(16) char smem[];

    const int tid  = threadIdx.x;
    const int lane = tid & 31;
    const int w    = tid >> 5;              // y-row of this warp's m-tile
    const int g    = lane >> 2;
    const int tig  = lane & 3;

    const int b  = blockIdx.z;
    const int y0 = blockIdx.y * TY;
    const int x0 = blockIdx.x * TX;

    const uint32_t sb = smem_to_u32(smem);
    char* pat = smem + SM_PATCH;
    const uint32_t patbase = sb + SM_PATCH;
    const uint32_t laneoff =
        (uint32_t)(((lane & 7) + ((lane >> 3) & 1) * 8) * PITCH + (lane >> 4) * 16);

    float acc[8][4];
#pragma unroll
    for (int nb = 0; nb < 8; nb++)
#pragma unroll
        for (int q = 0; q < 4; q++) acc[nb][q] = 0.f;

    const float* xb = x + (size_t)b * CIN * HW * HW;

    for (int chunk = 0; chunk < 4; chunk++) {
        __syncthreads();   // previous chunk's SMEM reads complete

        // ---- cp.async: this chunk's B slice (16 taps x 4KB = 64KB) ----
        {
            const uint4* src = g_wperm + chunk * 256 + tid;
#pragma unroll
            for (int t = 0; t < 16; t++)
                cp_async16(sb + SM_B + (uint32_t)(t * 256 + tid) * 16,
                           src + t * 1024);
            CP_COMMIT();
        }

        // ---- stage patch: 16 cin x 209 px, fp32 -> bf16 hi/lo ----
        for (int idx = tid; idx < STAGE_N; idx += 256) {
            int cl = idx / NPX;
            int px = idx - cl * NPX;
            int py = px / IX, pxx = px - py * IX;
            int gy = y0 + py - 1, gx = x0 + pxx - 1;
            float v = 0.f;
            if ((unsigned)gy < (unsigned)HW && (unsigned)gx < (unsigned)HW)
                v = xb[((size_t)(chunk * 16 + cl) * HW + gy) * HW + gx];
            __nv_bfloat16 h = __float2bfloat16(v);
            __nv_bfloat16 l = __float2bfloat16(v - __bfloat162float(h));
            *(__nv_bfloat16*)(pat + px * PITCH + cl * 2) = h;
            *(__nv_bfloat16*)(pat + PHALF + px * PITCH + cl * 2) = l;
        }
        CP_WAIT0();
        __syncthreads();

#pragma unroll
        for (int tap = 0; tap < 16; tap++) {
            const int dy = tap >> 2, dx = tap & 3;

            // ---- B: 8 conflict-free LDS.128 from staged SMEM ----
            // hi: (nh,part) = (0,0)(0,1)(1,0)(1,1) -> nb pairs (0,1)(2,3)(4,5)(6,7)
            // lo: same +1024 B (parts 2,3)
            uint32_t bh[8][2], bl[8][2];
#pragma unroll
            for (int j = 0; j < 4; j++) {
                const uint32_t a0 = sb + SM_B +
                    (uint32_t)(tap * 4096 + (j >> 1) * 2048 + (j & 1) * 512 +
                               lane * 16);
                uint32_t r0, r1, r2, r3;
                LDS128(r0, r1, r2, r3, a0);
                bh[j * 2][0] = r0; bh[j * 2][1] = r1;
                bh[j * 2 + 1][0] = r2; bh[j * 2 + 1][1] = r3;
                LDS128(r0, r1, r2, r3, a0 + 1024);
                bl[j * 2][0] = r0; bl[j * 2][1] = r1;
                bl[j * 2 + 1][0] = r2; bl[j * 2 + 1][1] = r3;
            }

            // ---- A: 2 LDSM for this warp's single m-tile ----
            const int sy = w + dy;
            const uint32_t abase =
                patbase + (uint32_t)((sy * IX + dx) * PITCH) + laneoff;
            uint32_t ah[4], al[4];
            LDSM4(ah, abase);
            LDSM4(al, abase + PHALF);

            // ---- 24 MMAs: prod-outer, nb-inner (8 independent chains) ----
#pragma unroll
            for (int prod = 0; prod < 3; prod++) {
                const uint32_t* a = (prod == 2) ? al : ah;
#pragma unroll
                for (int nb = 0; nb < 8; nb++) {
                    const uint32_t* bb = (prod == 1) ? bl[nb] : bh[nb];
                    MMA16816(acc[nb], a, bb);
                }
            }
        }
    }

    // ---- epilogue ----
    // c-frag: c0=(x=g, cout=n), c1=(x=g, cout=n+1), c2=(x=g+8, n), c3=(g+8, n+1)
    {
        const int gy = y0 + w;
#pragma unroll
        for (int nb = 0; nb < 8; nb++) {
            const int n = nb * 8 + tig * 2;
            float* o0 = out + ((size_t)b * COUT + n) * (HW * HW) + (size_t)gy * HW;
            float* o1 = o0 + (size_t)(HW * HW);
            o0[x0 + g]     = acc[nb][0];
            o1[x0 + g]     = acc[nb][1];
            o0[x0 + g + 8] = acc[nb][2];
            o1[x0 + g + 8] = acc[nb][3];
        }
    }
}

extern "C" void kernel_launch(void* const* d_in, const int* in_sizes, int n_in,
                              void* d_out, int out_size) {
    const float* x   = (const float*)d_in[0];
    const float* w   = (const float*)d_in[1];
    const float* off = (const float*)d_in[2];
    float* out = (float*)d_out;

    cudaFuncSetAttribute(conv_hmma_kernel,
                         cudaFuncAttributeMaxDynamicSharedMemorySize, SMEM_TOTAL);

    prep_kernel<<<(COUT * CIN + 255) / 256, 256>>>(w, off);

    dim3 grid(HW / TX, HW / TY, B_);   // (8, 16, 8) = 1024 CTAs
    conv_hmma_kernel<<<grid, 256, SMEM_TOTAL>>>(x, out);
}